// round 6
// baseline (speedup 1.0000x reference)
#include <cuda_runtime.h>
#include <cuda_bf16.h>
#include <math.h>
#include <stdint.h>

#define N_NODES 50000
#define N_EDGES 600000
#define NF      128
#define NG      512
#define NC      10
#define BN_EPS  1e-5f

// ---------------- scratch (device globals) ---------------------------------
__device__ int      g_deg   [N_NODES];
__device__ int      g_rowptr[N_NODES + 1];
__device__ int      g_cursor[N_NODES];
__device__ int      g_csrc  [N_EDGES];
__device__ float    g_dinv  [N_NODES];
__device__ float    g_y     [N_NODES * NF];
__device__ float    g_h     [N_NODES * NF];
__device__ unsigned g_gmax  [NG * NF];
__device__ float    g_g     [NG * NF];
__device__ float    g_m1    [NG * NF];
__device__ float    g_m2    [NG * 64];
// B fragments for mma.sync m16n8k16, pre-laid-out in register order:
// [L(4)][kc(4)][s(2)][nt(16)][hl(2)][lane(32)][j(2)] as uint32 (bf16x2)
__device__ unsigned g_bfrag[4 * 4 * 2 * 16 * 2 * 32 * 2];

// ---------------- helpers --------------------------------------------------
__device__ __forceinline__ unsigned enc_f(float v) {
    unsigned u = __float_as_uint(v);
    return (u & 0x80000000u) ? ~u : (u | 0x80000000u);
}
__device__ __forceinline__ float dec_f(unsigned u) {
    return (u & 0x80000000u) ? __uint_as_float(u & 0x7FFFFFFFu)
                             : __uint_as_float(~u);
}

// ---------------- CSR build -------------------------------------------------
// zero g_deg (n=N_NODES ints) and g_gmax (NG*NF uints) in one kernel
__global__ void zero_all() {
    int i = blockIdx.x * blockDim.x + threadIdx.x;
    if (i < N_NODES) g_deg[i] = 0;
    if (i < NG * NF) g_gmax[i] = 0u;
}
__global__ void deg_count(const int* __restrict__ dst) {
    int e = blockIdx.x * blockDim.x + threadIdx.x;
    if (e < N_EDGES) atomicAdd(&g_deg[dst[e]], 1);
}
__global__ __launch_bounds__(1024) void scan_deg() {
    __shared__ int sums[1024];
    const int CH = (N_NODES + 1023) / 1024;
    int t = threadIdx.x;
    int base = t * CH;
    int s = 0;
    for (int i = 0; i < CH; ++i) {
        int idx = base + i;
        if (idx < N_NODES) s += g_deg[idx];
    }
    sums[t] = s;
    __syncthreads();
    for (int off = 1; off < 1024; off <<= 1) {
        int v = 0;
        if (t >= off) v = sums[t - off];
        __syncthreads();
        if (t >= off) sums[t] += v;
        __syncthreads();
    }
    int run = (t == 0) ? 0 : sums[t - 1];
    for (int i = 0; i < CH; ++i) {
        int idx = base + i;
        if (idx < N_NODES) {
            g_rowptr[idx] = run;
            g_cursor[idx] = run;
            g_dinv[idx]   = rsqrtf((float)g_deg[idx] + 1.0f);
            run += g_deg[idx];
        }
    }
    if (t == 1023) g_rowptr[N_NODES] = run;
}
__global__ void csr_fill(const int* __restrict__ src, const int* __restrict__ dst) {
    int e = blockIdx.x * blockDim.x + threadIdx.x;
    if (e < N_EDGES) {
        int pos = atomicAdd(&g_cursor[dst[e]], 1);
        g_csrc[pos] = src[e];
    }
}

// ---------------- W pre-convert into mma B-fragment layout ------------------
__global__ void prep_w(const float* __restrict__ W1, const float* __restrict__ W2,
                       const float* __restrict__ W3, const float* __restrict__ LW1) {
    int i = blockIdx.x * blockDim.x + threadIdx.x;
    if (i >= 4 * NF * NF) return;
    int L = i >> 14;
    int r = i & 16383;
    int k = r >> 7;
    int n = r & 127;
    const float* W = (L == 0) ? W1 : (L == 1) ? W2 : (L == 2) ? W3 : LW1;
    float v = W[k * NF + n];
    __nv_bfloat16 hi = __float2bfloat16(v);
    __nv_bfloat16 lo = __float2bfloat16(v - __bfloat162float(hi));
    int kc = k >> 5;
    int s  = (k >> 4) & 1;
    int ko = k & 15;
    int nt = n >> 3;
    int lane = (n & 7) * 4 + ((ko & 7) >> 1);
    int j    = ko >> 3;
    int half = ko & 1;
    unsigned short* p = reinterpret_cast<unsigned short*>(g_bfrag);
    size_t bh = (((((size_t)((L * 4 + kc) * 2 + s) * 16 + nt) * 2 + 0) * 32 + lane) * 2 + j) * 2 + half;
    size_t bl = (((((size_t)((L * 4 + kc) * 2 + s) * 16 + nt) * 2 + 1) * 32 + lane) * 2 + j) * 2 + half;
    p[bh] = __bfloat16_as_ushort(hi);
    p[bl] = __bfloat16_as_ushort(lo);
}

// ---------------- mma.sync GEMM: out = (A @ W_L) * dinv  [+bias][relu] ------
// 128x128 CTA tile, 8 warps x (32 rows x 64 cols), K chunks of 32,
// bf16 hi/lo 3-pass split, fp32 accumulate, register-pipelined A loads.
#define ASTRIDE 20

__device__ __forceinline__ void mma_bf16(float* d, const unsigned* a, unsigned b0, unsigned b1) {
    asm volatile(
        "mma.sync.aligned.m16n8k16.row.col.f32.bf16.bf16.f32 "
        "{%0,%1,%2,%3}, {%4,%5,%6,%7}, {%8,%9}, {%0,%1,%2,%3};"
        : "+f"(d[0]), "+f"(d[1]), "+f"(d[2]), "+f"(d[3])
        : "r"(a[0]), "r"(a[1]), "r"(a[2]), "r"(a[3]), "r"(b0), "r"(b1));
}

__global__ __launch_bounds__(256)
void gemm_mma(const float* __restrict__ A, int L, float* __restrict__ out,
              const float* __restrict__ dinv, const float* __restrict__ bias,
              int nrows, int do_relu)
{
    __shared__ unsigned AshH[128 * ASTRIDE];
    __shared__ unsigned AshL[128 * ASTRIDE];

    const int tid   = threadIdx.x;
    const int warp  = tid >> 5;
    const int lane  = tid & 31;
    const int l4    = lane >> 2;
    const int lm    = lane & 3;
    const int mrowg = (warp & 3) * 32;
    const int ncolg = (warp >> 2) * 64;
    const int row0  = blockIdx.x * 128;

    float d[2][8][4];
    #pragma unroll
    for (int mt = 0; mt < 2; ++mt)
        #pragma unroll
        for (int nt = 0; nt < 8; ++nt)
            #pragma unroll
            for (int q = 0; q < 4; ++q) d[mt][nt][q] = 0.f;

    const int arow  = tid >> 1;
    const int ahalf = tid & 1;
    const int gr    = row0 + arow;
    const bool arok = (gr < nrows);

    // prefetch kc=0
    float4 pre[4];
    #pragma unroll
    for (int q = 0; q < 4; ++q)
        pre[q] = arok ? *reinterpret_cast<const float4*>(&A[gr * NF + ahalf * 16 + q * 4])
                      : make_float4(0.f, 0.f, 0.f, 0.f);

    for (int kc = 0; kc < 4; ++kc) {
        // ---- convert prefetched chunk into smem ----
        #pragma unroll
        for (int q = 0; q < 4; ++q) {
            float4 v = pre[q];
            __nv_bfloat16 hx = __float2bfloat16(v.x);
            __nv_bfloat16 hy = __float2bfloat16(v.y);
            __nv_bfloat16 hz = __float2bfloat16(v.z);
            __nv_bfloat16 hw = __float2bfloat16(v.w);
            unsigned hp0 = ((unsigned)__bfloat16_as_ushort(hy) << 16) | __bfloat16_as_ushort(hx);
            unsigned hp1 = ((unsigned)__bfloat16_as_ushort(hw) << 16) | __bfloat16_as_ushort(hz);
            __nv_bfloat16 lx = __float2bfloat16(v.x - __bfloat162float(hx));
            __nv_bfloat16 ly = __float2bfloat16(v.y - __bfloat162float(hy));
            __nv_bfloat16 lz = __float2bfloat16(v.z - __bfloat162float(hz));
            __nv_bfloat16 lw = __float2bfloat16(v.w - __bfloat162float(hw));
            unsigned lp0 = ((unsigned)__bfloat16_as_ushort(ly) << 16) | __bfloat16_as_ushort(lx);
            unsigned lp1 = ((unsigned)__bfloat16_as_ushort(lw) << 16) | __bfloat16_as_ushort(lz);
            int p = ahalf * 8 + q * 2;
            AshH[arow * ASTRIDE + p + 0] = hp0;
            AshH[arow * ASTRIDE + p + 1] = hp1;
            AshL[arow * ASTRIDE + p + 0] = lp0;
            AshL[arow * ASTRIDE + p + 1] = lp1;
        }
        __syncthreads();

        // ---- issue prefetch of next chunk (overlaps with MMA below) ----
        if (kc < 3) {
            #pragma unroll
            for (int q = 0; q < 4; ++q)
                pre[q] = arok ? *reinterpret_cast<const float4*>(
                                    &A[gr * NF + (kc + 1) * 32 + ahalf * 16 + q * 4])
                              : make_float4(0.f, 0.f, 0.f, 0.f);
        }

        #pragma unroll
        for (int s = 0; s < 2; ++s) {
            unsigned aH[2][4], aL[2][4];
            #pragma unroll
            for (int mt = 0; mt < 2; ++mt) {
                int rbase = mrowg + mt * 16;
                int p0 = s * 8 + lm;
                aH[mt][0] = AshH[(rbase + l4)     * ASTRIDE + p0];
                aH[mt][1] = AshH[(rbase + l4 + 8) * ASTRIDE + p0];
                aH[mt][2] = AshH[(rbase + l4)     * ASTRIDE + p0 + 4];
                aH[mt][3] = AshH[(rbase + l4 + 8) * ASTRIDE + p0 + 4];
                aL[mt][0] = AshL[(rbase + l4)     * ASTRIDE + p0];
                aL[mt][1] = AshL[(rbase + l4 + 8) * ASTRIDE + p0];
                aL[mt][2] = AshL[(rbase + l4)     * ASTRIDE + p0 + 4];
                aL[mt][3] = AshL[(rbase + l4 + 8) * ASTRIDE + p0 + 4];
            }
            #pragma unroll
            for (int nt = 0; nt < 8; ++nt) {
                int ntg = (ncolg >> 3) + nt;
                size_t idx = (((size_t)((L * 4 + kc) * 2 + s) * 16 + ntg) * 2) * 64 + lane * 2;
                uint2 bH = *reinterpret_cast<const uint2*>(&g_bfrag[idx]);
                uint2 bL = *reinterpret_cast<const uint2*>(&g_bfrag[idx + 64]);
                #pragma unroll
                for (int mt = 0; mt < 2; ++mt) {
                    mma_bf16(d[mt][nt], aH[mt], bH.x, bH.y);
                    mma_bf16(d[mt][nt], aH[mt], bL.x, bL.y);
                    mma_bf16(d[mt][nt], aL[mt], bH.x, bH.y);
                }
            }
        }
        __syncthreads();
    }

    #pragma unroll
    for (int mt = 0; mt < 2; ++mt) {
        int r_lo = row0 + mrowg + mt * 16 + l4;
        int r_hi = r_lo + 8;
        float s_lo = 1.f, s_hi = 1.f;
        if (dinv) {
            if (r_lo < nrows) s_lo = dinv[r_lo];
            if (r_hi < nrows) s_hi = dinv[r_hi];
        }
        #pragma unroll
        for (int nt = 0; nt < 8; ++nt) {
            int col = ncolg + nt * 8 + lm * 2;
            float b0 = 0.f, b1 = 0.f;
            if (bias) { b0 = bias[col]; b1 = bias[col + 1]; }
            float2 v0 = make_float2(d[mt][nt][0] * s_lo + b0, d[mt][nt][1] * s_lo + b1);
            float2 v1 = make_float2(d[mt][nt][2] * s_hi + b0, d[mt][nt][3] * s_hi + b1);
            if (do_relu) {
                v0.x = fmaxf(v0.x, 0.f); v0.y = fmaxf(v0.y, 0.f);
                v1.x = fmaxf(v1.x, 0.f); v1.y = fmaxf(v1.y, 0.f);
            }
            if (r_lo < nrows)
                *reinterpret_cast<float2*>(&out[r_lo * NF + col]) = v0;
            if (r_hi < nrows)
                *reinterpret_cast<float2*>(&out[r_hi * NF + col]) = v1;
        }
    }
}

// ---------------- aggregate (CSR gather, shfl-broadcast indices) ------------
// MODE 0: h = relu(dinv*(sum + self) + bias)
// MODE 1: same, then BN(eval) + per-graph atomicMax (no h store)
template <int MODE>
__global__ __launch_bounds__(256)
void aggregate(const float* __restrict__ y, const float* __restrict__ bias,
               float* __restrict__ h,
               const int* __restrict__ batch,
               const float* __restrict__ gamma, const float* __restrict__ beta,
               const float* __restrict__ rmean, const float* __restrict__ rvar)
{
    int node = blockIdx.x * 8 + (threadIdx.x >> 5);
    int lane = threadIdx.x & 31;
    if (node >= N_NODES) return;

    int p0 = g_rowptr[node];
    int p1 = g_rowptr[node + 1];

    float4 a = make_float4(0.f, 0.f, 0.f, 0.f);
    for (int base = p0; base < p1; base += 32) {
        int cnt = min(32, p1 - base);
        // one coalesced load of up to 32 indices, then shfl-broadcast
        int my = (base + lane < p1) ? g_csrc[base + lane] : 0;
        int j = 0;
        for (; j + 4 <= cnt; j += 4) {
            int s0 = __shfl_sync(0xFFFFFFFFu, my, j + 0);
            int s1 = __shfl_sync(0xFFFFFFFFu, my, j + 1);
            int s2 = __shfl_sync(0xFFFFFFFFu, my, j + 2);
            int s3 = __shfl_sync(0xFFFFFFFFu, my, j + 3);
            float4 v0 = *reinterpret_cast<const float4*>(&y[s0 * 128 + lane * 4]);
            float4 v1 = *reinterpret_cast<const float4*>(&y[s1 * 128 + lane * 4]);
            float4 v2 = *reinterpret_cast<const float4*>(&y[s2 * 128 + lane * 4]);
            float4 v3 = *reinterpret_cast<const float4*>(&y[s3 * 128 + lane * 4]);
            a.x += (v0.x + v1.x) + (v2.x + v3.x);
            a.y += (v0.y + v1.y) + (v2.y + v3.y);
            a.z += (v0.z + v1.z) + (v2.z + v3.z);
            a.w += (v0.w + v1.w) + (v2.w + v3.w);
        }
        for (; j < cnt; ++j) {
            int s = __shfl_sync(0xFFFFFFFFu, my, j);
            float4 v = *reinterpret_cast<const float4*>(&y[s * 128 + lane * 4]);
            a.x += v.x; a.y += v.y; a.z += v.z; a.w += v.w;
        }
    }

    float4 self = *reinterpret_cast<const float4*>(&y[node * 128 + lane * 4]);
    float  di   = g_dinv[node];
    int    c    = lane * 4;
    float4 bv   = *reinterpret_cast<const float4*>(&bias[c]);
    float4 o;
    o.x = fmaxf(di * (a.x + self.x) + bv.x, 0.f);
    o.y = fmaxf(di * (a.y + self.y) + bv.y, 0.f);
    o.z = fmaxf(di * (a.z + self.z) + bv.z, 0.f);
    o.w = fmaxf(di * (a.w + self.w) + bv.w, 0.f);

    if (MODE == 0) {
        *reinterpret_cast<float4*>(&h[node * 128 + c]) = o;
    } else {
        float4 gm = *reinterpret_cast<const float4*>(&gamma[c]);
        float4 bt = *reinterpret_cast<const float4*>(&beta[c]);
        float4 mu = *reinterpret_cast<const float4*>(&rmean[c]);
        float4 va = *reinterpret_cast<const float4*>(&rvar[c]);
        float4 v;
        v.x = (o.x - mu.x) * rsqrtf(va.x + BN_EPS) * gm.x + bt.x;
        v.y = (o.y - mu.y) * rsqrtf(va.y + BN_EPS) * gm.y + bt.y;
        v.z = (o.z - mu.z) * rsqrtf(va.z + BN_EPS) * gm.z + bt.z;
        v.w = (o.w - mu.w) * rsqrtf(va.w + BN_EPS) * gm.w + bt.w;
        unsigned* p = &g_gmax[batch[node] * 128 + c];
        atomicMax(p + 0, enc_f(v.x));
        atomicMax(p + 1, enc_f(v.y));
        atomicMax(p + 2, enc_f(v.z));
        atomicMax(p + 3, enc_f(v.w));
    }
}

__global__ void decode_g() {
    int i = blockIdx.x * blockDim.x + threadIdx.x;
    if (i < NG * NF) g_g[i] = dec_f(g_gmax[i]);
}

// ---------------- small GEMM (one block per row) ---------------------------
__global__ void small_gemm(const float* __restrict__ A, const float* __restrict__ W,
                           const float* __restrict__ b, float* __restrict__ out,
                           int K, int ncols, int do_relu)
{
    __shared__ float xs[128];
    int row = blockIdx.x;
    for (int k = threadIdx.x; k < K; k += blockDim.x) xs[k] = A[row * K + k];
    __syncthreads();
    int c = threadIdx.x;
    if (c < ncols) {
        float s = b[c];
        for (int k = 0; k < K; ++k) s += xs[k] * W[k * ncols + c];
        out[row * ncols + c] = do_relu ? fmaxf(s, 0.f) : s;
    }
}

// ---------------- launch ---------------------------------------------------
extern "C" void kernel_launch(void* const* d_in, const int* in_sizes, int n_in,
                              void* d_out, int out_size)
{
    const float* x     = (const float*)d_in[0];
    const int*   ei    = (const int*)  d_in[1];
    const int*   batch = (const int*)  d_in[2];
    const float* W1 = (const float*)d_in[3];  const float* b1 = (const float*)d_in[4];
    const float* W2 = (const float*)d_in[5];  const float* b2 = (const float*)d_in[6];
    const float* W3 = (const float*)d_in[7];  const float* b3 = (const float*)d_in[8];
    const float* gamma = (const float*)d_in[9];
    const float* beta  = (const float*)d_in[10];
    const float* rmean = (const float*)d_in[11];
    const float* rvar  = (const float*)d_in[12];
    const float* lw1 = (const float*)d_in[13]; const float* lb1 = (const float*)d_in[14];
    const float* lw2 = (const float*)d_in[15]; const float* lb2 = (const float*)d_in[16];
    const float* lw3 = (const float*)d_in[17]; const float* lb3 = (const float*)d_in[18];
    float* out = (float*)d_out;

    const int* src = ei;
    const int* dst = ei + N_EDGES;

    void *p_dinv, *p_y, *p_h, *p_g, *p_m1, *p_m2;
    cudaGetSymbolAddress(&p_dinv, g_dinv);
    cudaGetSymbolAddress(&p_y,    g_y);
    cudaGetSymbolAddress(&p_h,    g_h);
    cudaGetSymbolAddress(&p_g,    g_g);
    cudaGetSymbolAddress(&p_m1,   g_m1);
    cudaGetSymbolAddress(&p_m2,   g_m2);
    float* y = (float*)p_y;
    float* h = (float*)p_h;
    const float* dinv = (const float*)p_dinv;

    const int EB = (N_EDGES + 255) / 256;
    const int ZB = (((N_NODES > NG * NF) ? N_NODES : NG * NF) + 255) / 256;
    const int GRID_GEMM = (N_NODES + 127) / 128;
    const int GRID_AGG  = (N_NODES + 7) / 8;

    // CSR build + dinv + weight fragment prep
    zero_all<<<ZB, 256>>>();
    deg_count<<<EB, 256>>>(dst);
    scan_deg<<<1, 1024>>>();
    csr_fill<<<EB, 256>>>(src, dst);
    prep_w<<<(4 * NF * NF + 255) / 256, 256>>>(W1, W2, W3, lw1);

    // layer 1
    gemm_mma<<<GRID_GEMM, 256>>>(x, 0, y, dinv, nullptr, N_NODES, 0);
    aggregate<0><<<GRID_AGG, 256>>>(y, b1, h, nullptr, nullptr, nullptr, nullptr, nullptr);
    // layer 2
    gemm_mma<<<GRID_GEMM, 256>>>(h, 1, y, dinv, nullptr, N_NODES, 0);
    aggregate<0><<<GRID_AGG, 256>>>(y, b2, h, nullptr, nullptr, nullptr, nullptr, nullptr);
    // layer 3 + BN + pool
    gemm_mma<<<GRID_GEMM, 256>>>(h, 2, y, dinv, nullptr, N_NODES, 0);
    aggregate<1><<<GRID_AGG, 256>>>(y, b3, nullptr, batch, gamma, beta, rmean, rvar);

    decode_g<<<(NG * NF + 255) / 256, 256>>>();

    // MLP head
    gemm_mma<<<(NG + 127) / 128, 256>>>((const float*)p_g, 3, (float*)p_m1,
                                        nullptr, lb1, NG, 1);
    small_gemm<<<NG, 64>>>((const float*)p_m1, lw2, lb2, (float*)p_m2, 128, 64, 1);
    small_gemm<<<NG, 64>>>((const float*)p_m2, lw3, lb3, out, 64, NC, 0);
}

// round 7
// speedup vs baseline: 1.1174x; 1.1174x over previous
#include <cuda_runtime.h>
#include <cuda_bf16.h>
#include <math.h>
#include <stdint.h>

#define N_NODES 50000
#define N_EDGES 600000
#define NF      128
#define NG      512
#define NC      10
#define BN_EPS  1e-5f

// ---------------- scratch (device globals) ---------------------------------
__device__ int      g_deg   [N_NODES];
__device__ int      g_rowptr[N_NODES + 1];
__device__ int      g_cursor[N_NODES];
__device__ int      g_csrc  [N_EDGES];
__device__ float    g_dinv  [N_NODES];
__device__ float    g_y     [N_NODES * NF];
__device__ float    g_h     [N_NODES * NF];
__device__ unsigned g_gmax  [NG * NF];
__device__ float    g_g     [NG * NF];
__device__ float    g_m1    [NG * NF];
__device__ float    g_m2    [NG * 64];
// B fragments for mma.sync m16n8k16, pre-laid-out in register order:
// [L(4)][kc(4)][s(2)][nt(16)][hl(2)][lane(32)][j(2)] as uint32 (bf16x2)
__device__ unsigned g_bfrag[4 * 4 * 2 * 16 * 2 * 32 * 2];

// ---------------- helpers --------------------------------------------------
__device__ __forceinline__ unsigned enc_f(float v) {
    unsigned u = __float_as_uint(v);
    return (u & 0x80000000u) ? ~u : (u | 0x80000000u);
}
__device__ __forceinline__ float dec_f(unsigned u) {
    return (u & 0x80000000u) ? __uint_as_float(u & 0x7FFFFFFFu)
                             : __uint_as_float(~u);
}

// ---------------- CSR build -------------------------------------------------
__global__ void zero_all() {
    int i = blockIdx.x * blockDim.x + threadIdx.x;
    if (i < N_NODES) g_deg[i] = 0;
    if (i < NG * NF) g_gmax[i] = 0u;
}
__global__ void deg_count(const int* __restrict__ dst) {
    int e = blockIdx.x * blockDim.x + threadIdx.x;
    if (e < N_EDGES) atomicAdd(&g_deg[dst[e]], 1);
}
__global__ __launch_bounds__(1024) void scan_deg() {
    __shared__ int sums[1024];
    const int CH = (N_NODES + 1023) / 1024;
    int t = threadIdx.x;
    int base = t * CH;
    int s = 0;
    for (int i = 0; i < CH; ++i) {
        int idx = base + i;
        if (idx < N_NODES) s += g_deg[idx];
    }
    sums[t] = s;
    __syncthreads();
    for (int off = 1; off < 1024; off <<= 1) {
        int v = 0;
        if (t >= off) v = sums[t - off];
        __syncthreads();
        if (t >= off) sums[t] += v;
        __syncthreads();
    }
    int run = (t == 0) ? 0 : sums[t - 1];
    for (int i = 0; i < CH; ++i) {
        int idx = base + i;
        if (idx < N_NODES) {
            g_rowptr[idx] = run;
            g_cursor[idx] = run;
            g_dinv[idx]   = rsqrtf((float)g_deg[idx] + 1.0f);
            run += g_deg[idx];
        }
    }
    if (t == 1023) g_rowptr[N_NODES] = run;
}
__global__ void csr_fill(const int* __restrict__ src, const int* __restrict__ dst) {
    int e = blockIdx.x * blockDim.x + threadIdx.x;
    if (e < N_EDGES) {
        int pos = atomicAdd(&g_cursor[dst[e]], 1);
        g_csrc[pos] = src[e];
    }
}

// ---------------- W pre-convert into mma B-fragment layout ------------------
__global__ void prep_w(const float* __restrict__ W1, const float* __restrict__ W2,
                       const float* __restrict__ W3, const float* __restrict__ LW1) {
    int i = blockIdx.x * blockDim.x + threadIdx.x;
    if (i >= 4 * NF * NF) return;
    int L = i >> 14;
    int r = i & 16383;
    int k = r >> 7;
    int n = r & 127;
    const float* W = (L == 0) ? W1 : (L == 1) ? W2 : (L == 2) ? W3 : LW1;
    float v = W[k * NF + n];
    __nv_bfloat16 hi = __float2bfloat16(v);
    __nv_bfloat16 lo = __float2bfloat16(v - __bfloat162float(hi));
    int kc = k >> 5;
    int s  = (k >> 4) & 1;
    int ko = k & 15;
    int nt = n >> 3;
    int lane = (n & 7) * 4 + ((ko & 7) >> 1);
    int j    = ko >> 3;
    int half = ko & 1;
    unsigned short* p = reinterpret_cast<unsigned short*>(g_bfrag);
    size_t bh = (((((size_t)((L * 4 + kc) * 2 + s) * 16 + nt) * 2 + 0) * 32 + lane) * 2 + j) * 2 + half;
    size_t bl = (((((size_t)((L * 4 + kc) * 2 + s) * 16 + nt) * 2 + 1) * 32 + lane) * 2 + j) * 2 + half;
    p[bh] = __bfloat16_as_ushort(hi);
    p[bl] = __bfloat16_as_ushort(lo);
}

// ---------------- mma.sync GEMM: out = (A @ W_L) [* dinv] [+bias][relu] -----
// 128x128 CTA tile, 8 warps x (32 rows x 64 cols), K chunks of 32,
// bf16 hi/lo 3-pass split, fp32 accumulate.  (R5 version — no reg prefetch.)
#define ASTRIDE 20

__device__ __forceinline__ void mma_bf16(float* d, const unsigned* a, unsigned b0, unsigned b1) {
    asm volatile(
        "mma.sync.aligned.m16n8k16.row.col.f32.bf16.bf16.f32 "
        "{%0,%1,%2,%3}, {%4,%5,%6,%7}, {%8,%9}, {%0,%1,%2,%3};"
        : "+f"(d[0]), "+f"(d[1]), "+f"(d[2]), "+f"(d[3])
        : "r"(a[0]), "r"(a[1]), "r"(a[2]), "r"(a[3]), "r"(b0), "r"(b1));
}

__global__ __launch_bounds__(256)
void gemm_mma(const float* __restrict__ A, int L, float* __restrict__ out,
              const float* __restrict__ dinv, const float* __restrict__ bias,
              int nrows, int do_relu)
{
    __shared__ unsigned AshH[128 * ASTRIDE];
    __shared__ unsigned AshL[128 * ASTRIDE];

    const int tid   = threadIdx.x;
    const int warp  = tid >> 5;
    const int lane  = tid & 31;
    const int l4    = lane >> 2;
    const int lm    = lane & 3;
    const int mrowg = (warp & 3) * 32;
    const int ncolg = (warp >> 2) * 64;
    const int row0  = blockIdx.x * 128;

    float d[2][8][4];
    #pragma unroll
    for (int mt = 0; mt < 2; ++mt)
        #pragma unroll
        for (int nt = 0; nt < 8; ++nt)
            #pragma unroll
            for (int q = 0; q < 4; ++q) d[mt][nt][q] = 0.f;

    const int arow  = tid >> 1;
    const int ahalf = tid & 1;

    for (int kc = 0; kc < 4; ++kc) {
        {
            int gr = row0 + arow;
            #pragma unroll
            for (int q = 0; q < 4; ++q) {
                float4 v = make_float4(0.f, 0.f, 0.f, 0.f);
                if (gr < nrows)
                    v = *reinterpret_cast<const float4*>(
                        &A[gr * NF + kc * 32 + ahalf * 16 + q * 4]);
                __nv_bfloat16 hx = __float2bfloat16(v.x);
                __nv_bfloat16 hy = __float2bfloat16(v.y);
                __nv_bfloat16 hz = __float2bfloat16(v.z);
                __nv_bfloat16 hw = __float2bfloat16(v.w);
                unsigned hp0 = ((unsigned)__bfloat16_as_ushort(hy) << 16) | __bfloat16_as_ushort(hx);
                unsigned hp1 = ((unsigned)__bfloat16_as_ushort(hw) << 16) | __bfloat16_as_ushort(hz);
                __nv_bfloat16 lx = __float2bfloat16(v.x - __bfloat162float(hx));
                __nv_bfloat16 ly = __float2bfloat16(v.y - __bfloat162float(hy));
                __nv_bfloat16 lz = __float2bfloat16(v.z - __bfloat162float(hz));
                __nv_bfloat16 lw = __float2bfloat16(v.w - __bfloat162float(hw));
                unsigned lp0 = ((unsigned)__bfloat16_as_ushort(ly) << 16) | __bfloat16_as_ushort(lx);
                unsigned lp1 = ((unsigned)__bfloat16_as_ushort(lw) << 16) | __bfloat16_as_ushort(lz);
                int p = ahalf * 8 + q * 2;
                AshH[arow * ASTRIDE + p + 0] = hp0;
                AshH[arow * ASTRIDE + p + 1] = hp1;
                AshL[arow * ASTRIDE + p + 0] = lp0;
                AshL[arow * ASTRIDE + p + 1] = lp1;
            }
        }
        __syncthreads();

        #pragma unroll
        for (int s = 0; s < 2; ++s) {
            unsigned aH[2][4], aL[2][4];
            #pragma unroll
            for (int mt = 0; mt < 2; ++mt) {
                int rbase = mrowg + mt * 16;
                int p0 = s * 8 + lm;
                aH[mt][0] = AshH[(rbase + l4)     * ASTRIDE + p0];
                aH[mt][1] = AshH[(rbase + l4 + 8) * ASTRIDE + p0];
                aH[mt][2] = AshH[(rbase + l4)     * ASTRIDE + p0 + 4];
                aH[mt][3] = AshH[(rbase + l4 + 8) * ASTRIDE + p0 + 4];
                aL[mt][0] = AshL[(rbase + l4)     * ASTRIDE + p0];
                aL[mt][1] = AshL[(rbase + l4 + 8) * ASTRIDE + p0];
                aL[mt][2] = AshL[(rbase + l4)     * ASTRIDE + p0 + 4];
                aL[mt][3] = AshL[(rbase + l4 + 8) * ASTRIDE + p0 + 4];
            }
            #pragma unroll
            for (int nt = 0; nt < 8; ++nt) {
                int ntg = (ncolg >> 3) + nt;
                size_t idx = (((size_t)((L * 4 + kc) * 2 + s) * 16 + ntg) * 2) * 64 + lane * 2;
                uint2 bH = *reinterpret_cast<const uint2*>(&g_bfrag[idx]);
                uint2 bL = *reinterpret_cast<const uint2*>(&g_bfrag[idx + 64]);
                #pragma unroll
                for (int mt = 0; mt < 2; ++mt) {
                    mma_bf16(d[mt][nt], aH[mt], bH.x, bH.y);
                    mma_bf16(d[mt][nt], aH[mt], bL.x, bL.y);
                    mma_bf16(d[mt][nt], aL[mt], bH.x, bH.y);
                }
            }
        }
        __syncthreads();
    }

    #pragma unroll
    for (int mt = 0; mt < 2; ++mt) {
        int r_lo = row0 + mrowg + mt * 16 + l4;
        int r_hi = r_lo + 8;
        float s_lo = 1.f, s_hi = 1.f;
        if (dinv) {
            if (r_lo < nrows) s_lo = dinv[r_lo];
            if (r_hi < nrows) s_hi = dinv[r_hi];
        }
        #pragma unroll
        for (int nt = 0; nt < 8; ++nt) {
            int col = ncolg + nt * 8 + lm * 2;
            float b0 = 0.f, b1 = 0.f;
            if (bias) { b0 = bias[col]; b1 = bias[col + 1]; }
            float2 v0 = make_float2(d[mt][nt][0] * s_lo + b0, d[mt][nt][1] * s_lo + b1);
            float2 v1 = make_float2(d[mt][nt][2] * s_hi + b0, d[mt][nt][3] * s_hi + b1);
            if (do_relu) {
                v0.x = fmaxf(v0.x, 0.f); v0.y = fmaxf(v0.y, 0.f);
                v1.x = fmaxf(v1.x, 0.f); v1.y = fmaxf(v1.y, 0.f);
            }
            if (r_lo < nrows)
                *reinterpret_cast<float2*>(&out[r_lo * NF + col]) = v0;
            if (r_hi < nrows)
                *reinterpret_cast<float2*>(&out[r_hi * NF + col]) = v1;
        }
    }
}

// ---------------- aggregate (CSR gather) + fused epilogue ------------------
// MODE 0: y pre-scaled by dinv:  h = relu(dinv*(sum + self) + bias)
// MODE 1: as 0, then BN(eval) + per-graph atomicMax (no h store)
// MODE 2: y UNscaled: h = relu(dinv*(sum_src dinv[s]*y[s] + dinv*self) + bias)
template <int MODE>
__global__ __launch_bounds__(256)
void aggregate(const float* __restrict__ y, const float* __restrict__ bias,
               float* __restrict__ h,
               const int* __restrict__ batch,
               const float* __restrict__ gamma, const float* __restrict__ beta,
               const float* __restrict__ rmean, const float* __restrict__ rvar)
{
    int node = blockIdx.x * 8 + (threadIdx.x >> 5);
    int lane = threadIdx.x & 31;
    if (node >= N_NODES) return;

    int p0 = g_rowptr[node];
    int p1 = g_rowptr[node + 1];

    float4 a = make_float4(0.f, 0.f, 0.f, 0.f);
    int e = p0;
    for (; e + 4 <= p1; e += 4) {
        int s0 = g_csrc[e + 0];
        int s1 = g_csrc[e + 1];
        int s2 = g_csrc[e + 2];
        int s3 = g_csrc[e + 3];
        float4 v0 = *reinterpret_cast<const float4*>(&y[s0 * 128 + lane * 4]);
        float4 v1 = *reinterpret_cast<const float4*>(&y[s1 * 128 + lane * 4]);
        float4 v2 = *reinterpret_cast<const float4*>(&y[s2 * 128 + lane * 4]);
        float4 v3 = *reinterpret_cast<const float4*>(&y[s3 * 128 + lane * 4]);
        if (MODE == 2) {
            float d0 = g_dinv[s0], d1 = g_dinv[s1], d2 = g_dinv[s2], d3 = g_dinv[s3];
            a.x += v0.x * d0 + v1.x * d1 + v2.x * d2 + v3.x * d3;
            a.y += v0.y * d0 + v1.y * d1 + v2.y * d2 + v3.y * d3;
            a.z += v0.z * d0 + v1.z * d1 + v2.z * d2 + v3.z * d3;
            a.w += v0.w * d0 + v1.w * d1 + v2.w * d2 + v3.w * d3;
        } else {
            a.x += (v0.x + v1.x) + (v2.x + v3.x);
            a.y += (v0.y + v1.y) + (v2.y + v3.y);
            a.z += (v0.z + v1.z) + (v2.z + v3.z);
            a.w += (v0.w + v1.w) + (v2.w + v3.w);
        }
    }
    for (; e < p1; ++e) {
        int s = g_csrc[e];
        float4 v = *reinterpret_cast<const float4*>(&y[s * 128 + lane * 4]);
        float ds = (MODE == 2) ? g_dinv[s] : 1.f;
        a.x += v.x * ds; a.y += v.y * ds; a.z += v.z * ds; a.w += v.w * ds;
    }

    float4 self = *reinterpret_cast<const float4*>(&y[node * 128 + lane * 4]);
    float  di   = g_dinv[node];
    float  selfscale = (MODE == 2) ? di : 1.f;
    int    c    = lane * 4;
    float4 bv   = *reinterpret_cast<const float4*>(&bias[c]);
    float4 o;
    o.x = fmaxf(di * (a.x + self.x * selfscale) + bv.x, 0.f);
    o.y = fmaxf(di * (a.y + self.y * selfscale) + bv.y, 0.f);
    o.z = fmaxf(di * (a.z + self.z * selfscale) + bv.z, 0.f);
    o.w = fmaxf(di * (a.w + self.w * selfscale) + bv.w, 0.f);

    if (MODE != 1) {
        *reinterpret_cast<float4*>(&h[node * 128 + c]) = o;
    } else {
        float4 gm = *reinterpret_cast<const float4*>(&gamma[c]);
        float4 bt = *reinterpret_cast<const float4*>(&beta[c]);
        float4 mu = *reinterpret_cast<const float4*>(&rmean[c]);
        float4 va = *reinterpret_cast<const float4*>(&rvar[c]);
        float4 v;
        v.x = (o.x - mu.x) * rsqrtf(va.x + BN_EPS) * gm.x + bt.x;
        v.y = (o.y - mu.y) * rsqrtf(va.y + BN_EPS) * gm.y + bt.y;
        v.z = (o.z - mu.z) * rsqrtf(va.z + BN_EPS) * gm.z + bt.z;
        v.w = (o.w - mu.w) * rsqrtf(va.w + BN_EPS) * gm.w + bt.w;
        unsigned* p = &g_gmax[batch[node] * 128 + c];
        atomicMax(p + 0, enc_f(v.x));
        atomicMax(p + 1, enc_f(v.y));
        atomicMax(p + 2, enc_f(v.z));
        atomicMax(p + 3, enc_f(v.w));
    }
}

__global__ void decode_g() {
    int i = blockIdx.x * blockDim.x + threadIdx.x;
    if (i < NG * NF) g_g[i] = dec_f(g_gmax[i]);
}

// ---------------- small GEMM (one block per row) ---------------------------
__global__ void small_gemm(const float* __restrict__ A, const float* __restrict__ W,
                           const float* __restrict__ b, float* __restrict__ out,
                           int K, int ncols, int do_relu)
{
    __shared__ float xs[128];
    int row = blockIdx.x;
    for (int k = threadIdx.x; k < K; k += blockDim.x) xs[k] = A[row * K + k];
    __syncthreads();
    int c = threadIdx.x;
    if (c < ncols) {
        float s = b[c];
        for (int k = 0; k < K; ++k) s += xs[k] * W[k * ncols + c];
        out[row * ncols + c] = do_relu ? fmaxf(s, 0.f) : s;
    }
}

// ---------------- launch ---------------------------------------------------
extern "C" void kernel_launch(void* const* d_in, const int* in_sizes, int n_in,
                              void* d_out, int out_size)
{
    const float* x     = (const float*)d_in[0];
    const int*   ei    = (const int*)  d_in[1];
    const int*   batch = (const int*)  d_in[2];
    const float* W1 = (const float*)d_in[3];  const float* b1 = (const float*)d_in[4];
    const float* W2 = (const float*)d_in[5];  const float* b2 = (const float*)d_in[6];
    const float* W3 = (const float*)d_in[7];  const float* b3 = (const float*)d_in[8];
    const float* gamma = (const float*)d_in[9];
    const float* beta  = (const float*)d_in[10];
    const float* rmean = (const float*)d_in[11];
    const float* rvar  = (const float*)d_in[12];
    const float* lw1 = (const float*)d_in[13]; const float* lb1 = (const float*)d_in[14];
    const float* lw2 = (const float*)d_in[15]; const float* lb2 = (const float*)d_in[16];
    const float* lw3 = (const float*)d_in[17]; const float* lb3 = (const float*)d_in[18];
    float* out = (float*)d_out;

    const int* src = ei;
    const int* dst = ei + N_EDGES;

    void *p_dinv, *p_y, *p_h, *p_g, *p_m1, *p_m2;
    cudaGetSymbolAddress(&p_dinv, g_dinv);
    cudaGetSymbolAddress(&p_y,    g_y);
    cudaGetSymbolAddress(&p_h,    g_h);
    cudaGetSymbolAddress(&p_g,    g_g);
    cudaGetSymbolAddress(&p_m1,   g_m1);
    cudaGetSymbolAddress(&p_m2,   g_m2);
    float* y = (float*)p_y;
    float* h = (float*)p_h;
    const float* dinv = (const float*)p_dinv;

    const int EB = (N_EDGES + 255) / 256;
    const int ZB = (((N_NODES > NG * NF) ? N_NODES : NG * NF) + 255) / 256;
    const int GRID_GEMM = (N_NODES + 127) / 128;
    const int GRID_AGG  = (N_NODES + 7) / 8;

    // ---- fork: CSR build chain on a side stream, concurrent with gemm1 ----
    cudaStream_t s2;
    cudaEvent_t evA, evB;
    cudaStreamCreateWithFlags(&s2, cudaStreamNonBlocking);
    cudaEventCreateWithFlags(&evA, cudaEventDisableTiming);
    cudaEventCreateWithFlags(&evB, cudaEventDisableTiming);

    cudaEventRecord(evA, 0);
    cudaStreamWaitEvent(s2, evA, 0);
    zero_all<<<ZB, 256, 0, s2>>>();
    deg_count<<<EB, 256, 0, s2>>>(dst);
    scan_deg<<<1, 1024, 0, s2>>>();
    csr_fill<<<EB, 256, 0, s2>>>(src, dst);
    cudaEventRecord(evB, s2);

    // ---- main stream: weights + layer-1 GEMM (no dinv dependency) ----
    prep_w<<<(4 * NF * NF + 255) / 256, 256>>>(W1, W2, W3, lw1);
    gemm_mma<<<GRID_GEMM, 256>>>(x, 0, y, nullptr, nullptr, N_NODES, 0);

    // join CSR chain, then proceed
    cudaStreamWaitEvent(0, evB, 0);

    // layer 1 (aggregate applies dinv[src] itself)
    aggregate<2><<<GRID_AGG, 256>>>(y, b1, h, nullptr, nullptr, nullptr, nullptr, nullptr);
    // layer 2
    gemm_mma<<<GRID_GEMM, 256>>>(h, 1, y, dinv, nullptr, N_NODES, 0);
    aggregate<0><<<GRID_AGG, 256>>>(y, b2, h, nullptr, nullptr, nullptr, nullptr, nullptr);
    // layer 3 + BN + pool
    gemm_mma<<<GRID_GEMM, 256>>>(h, 2, y, dinv, nullptr, N_NODES, 0);
    aggregate<1><<<GRID_AGG, 256>>>(y, b3, nullptr, batch, gamma, beta, rmean, rvar);

    decode_g<<<(NG * NF + 255) / 256, 256>>>();

    // MLP head
    gemm_mma<<<(NG + 127) / 128, 256>>>((const float*)p_g, 3, (float*)p_m1,
                                        nullptr, lb1, NG, 1);
    small_gemm<<<NG, 64>>>((const float*)p_m1, lw2, lb2, (float*)p_m2, 128, 64, 1);
    small_gemm<<<NG, 64>>>((const float*)p_m2, lw3, lb3, out, 64, NC, 0);
}

// round 8
// speedup vs baseline: 1.1666x; 1.0441x over previous
#include <cuda_runtime.h>
#include <cuda_bf16.h>
#include <math.h>
#include <stdint.h>

#define N_NODES 50000
#define N_EDGES 600000
#define NF      128
#define NG      512
#define NC      10
#define BN_EPS  1e-5f

// ---------------- scratch (device globals) ---------------------------------
__device__ int      g_deg   [N_NODES];
__device__ int      g_rowptr[N_NODES + 1];
__device__ int      g_cursor[N_NODES];
__device__ int      g_csrc  [N_EDGES];
__device__ float    g_dinv  [N_NODES];
__device__ float    g_y     [N_NODES * NF];
__device__ float    g_h     [N_NODES * NF];
__device__ unsigned g_gmax  [NG * NF];
__device__ float    g_g     [NG * NF];
__device__ float    g_m1    [NG * NF];
__device__ float    g_m2    [NG * 64];
// B fragments for mma.sync m16n8k16, pre-laid-out in register order:
// [L(4)][kc(4)][s(2)][nt(16)][hl(2)][lane(32)][j(2)] as uint32 (bf16x2)
__device__ unsigned g_bfrag[4 * 4 * 2 * 16 * 2 * 32 * 2];

// ---------------- helpers --------------------------------------------------
__device__ __forceinline__ unsigned enc_f(float v) {
    unsigned u = __float_as_uint(v);
    return (u & 0x80000000u) ? ~u : (u | 0x80000000u);
}
__device__ __forceinline__ float dec_f(unsigned u) {
    return (u & 0x80000000u) ? __uint_as_float(u & 0x7FFFFFFFu)
                             : __uint_as_float(~u);
}

// ---------------- CSR build -------------------------------------------------
__global__ void zero_all() {
    int i = blockIdx.x * blockDim.x + threadIdx.x;
    if (i < N_NODES) g_deg[i] = 0;
    if (i < NG * NF) g_gmax[i] = 0u;
}
__global__ void deg_count(const int* __restrict__ dst) {
    int e = blockIdx.x * blockDim.x + threadIdx.x;
    if (e < N_EDGES) atomicAdd(&g_deg[dst[e]], 1);
}
__global__ __launch_bounds__(1024) void scan_deg() {
    __shared__ int sums[1024];
    const int CH = (N_NODES + 1023) / 1024;
    int t = threadIdx.x;
    int base = t * CH;
    int s = 0;
    for (int i = 0; i < CH; ++i) {
        int idx = base + i;
        if (idx < N_NODES) s += g_deg[idx];
    }
    sums[t] = s;
    __syncthreads();
    for (int off = 1; off < 1024; off <<= 1) {
        int v = 0;
        if (t >= off) v = sums[t - off];
        __syncthreads();
        if (t >= off) sums[t] += v;
        __syncthreads();
    }
    int run = (t == 0) ? 0 : sums[t - 1];
    for (int i = 0; i < CH; ++i) {
        int idx = base + i;
        if (idx < N_NODES) {
            g_rowptr[idx] = run;
            g_cursor[idx] = run;
            g_dinv[idx]   = rsqrtf((float)g_deg[idx] + 1.0f);
            run += g_deg[idx];
        }
    }
    if (t == 1023) g_rowptr[N_NODES] = run;
}
__global__ void csr_fill(const int* __restrict__ src, const int* __restrict__ dst) {
    int e = blockIdx.x * blockDim.x + threadIdx.x;
    if (e < N_EDGES) {
        int pos = atomicAdd(&g_cursor[dst[e]], 1);
        g_csrc[pos] = src[e];
    }
}

// ---------------- W pre-convert into mma B-fragment layout ------------------
__global__ void prep_w(const float* __restrict__ W1, const float* __restrict__ W2,
                       const float* __restrict__ W3, const float* __restrict__ LW1) {
    int i = blockIdx.x * blockDim.x + threadIdx.x;
    if (i >= 4 * NF * NF) return;
    int L = i >> 14;
    int r = i & 16383;
    int k = r >> 7;
    int n = r & 127;
    const float* W = (L == 0) ? W1 : (L == 1) ? W2 : (L == 2) ? W3 : LW1;
    float v = W[k * NF + n];
    __nv_bfloat16 hi = __float2bfloat16(v);
    __nv_bfloat16 lo = __float2bfloat16(v - __bfloat162float(hi));
    int kc = k >> 5;
    int s  = (k >> 4) & 1;
    int ko = k & 15;
    int nt = n >> 3;
    int lane = (n & 7) * 4 + ((ko & 7) >> 1);
    int j    = ko >> 3;
    int half = ko & 1;
    unsigned short* p = reinterpret_cast<unsigned short*>(g_bfrag);
    size_t bh = (((((size_t)((L * 4 + kc) * 2 + s) * 16 + nt) * 2 + 0) * 32 + lane) * 2 + j) * 2 + half;
    size_t bl = (((((size_t)((L * 4 + kc) * 2 + s) * 16 + nt) * 2 + 1) * 32 + lane) * 2 + j) * 2 + half;
    p[bh] = __bfloat16_as_ushort(hi);
    p[bl] = __bfloat16_as_ushort(lo);
}

// ---------------- mma.sync GEMM: out = (A @ W_L) [* dinv] [+bias][relu] -----
#define ASTRIDE 20

__device__ __forceinline__ void mma_bf16(float* d, const unsigned* a, unsigned b0, unsigned b1) {
    asm volatile(
        "mma.sync.aligned.m16n8k16.row.col.f32.bf16.bf16.f32 "
        "{%0,%1,%2,%3}, {%4,%5,%6,%7}, {%8,%9}, {%0,%1,%2,%3};"
        : "+f"(d[0]), "+f"(d[1]), "+f"(d[2]), "+f"(d[3])
        : "r"(a[0]), "r"(a[1]), "r"(a[2]), "r"(a[3]), "r"(b0), "r"(b1));
}

__global__ __launch_bounds__(256)
void gemm_mma(const float* __restrict__ A, int L, float* __restrict__ out,
              const float* __restrict__ dinv, const float* __restrict__ bias,
              int nrows, int do_relu)
{
    __shared__ unsigned AshH[128 * ASTRIDE];
    __shared__ unsigned AshL[128 * ASTRIDE];

    const int tid   = threadIdx.x;
    const int warp  = tid >> 5;
    const int lane  = tid & 31;
    const int l4    = lane >> 2;
    const int lm    = lane & 3;
    const int mrowg = (warp & 3) * 32;
    const int ncolg = (warp >> 2) * 64;
    const int row0  = blockIdx.x * 128;

    float d[2][8][4];
    #pragma unroll
    for (int mt = 0; mt < 2; ++mt)
        #pragma unroll
        for (int nt = 0; nt < 8; ++nt)
            #pragma unroll
            for (int q = 0; q < 4; ++q) d[mt][nt][q] = 0.f;

    const int arow  = tid >> 1;
    const int ahalf = tid & 1;

    for (int kc = 0; kc < 4; ++kc) {
        {
            int gr = row0 + arow;
            #pragma unroll
            for (int q = 0; q < 4; ++q) {
                float4 v = make_float4(0.f, 0.f, 0.f, 0.f);
                if (gr < nrows)
                    v = *reinterpret_cast<const float4*>(
                        &A[gr * NF + kc * 32 + ahalf * 16 + q * 4]);
                __nv_bfloat16 hx = __float2bfloat16(v.x);
                __nv_bfloat16 hy = __float2bfloat16(v.y);
                __nv_bfloat16 hz = __float2bfloat16(v.z);
                __nv_bfloat16 hw = __float2bfloat16(v.w);
                unsigned hp0 = ((unsigned)__bfloat16_as_ushort(hy) << 16) | __bfloat16_as_ushort(hx);
                unsigned hp1 = ((unsigned)__bfloat16_as_ushort(hw) << 16) | __bfloat16_as_ushort(hz);
                __nv_bfloat16 lx = __float2bfloat16(v.x - __bfloat162float(hx));
                __nv_bfloat16 ly = __float2bfloat16(v.y - __bfloat162float(hy));
                __nv_bfloat16 lz = __float2bfloat16(v.z - __bfloat162float(hz));
                __nv_bfloat16 lw = __float2bfloat16(v.w - __bfloat162float(hw));
                unsigned lp0 = ((unsigned)__bfloat16_as_ushort(ly) << 16) | __bfloat16_as_ushort(lx);
                unsigned lp1 = ((unsigned)__bfloat16_as_ushort(lw) << 16) | __bfloat16_as_ushort(lz);
                int p = ahalf * 8 + q * 2;
                AshH[arow * ASTRIDE + p + 0] = hp0;
                AshH[arow * ASTRIDE + p + 1] = hp1;
                AshL[arow * ASTRIDE + p + 0] = lp0;
                AshL[arow * ASTRIDE + p + 1] = lp1;
            }
        }
        __syncthreads();

        #pragma unroll
        for (int s = 0; s < 2; ++s) {
            unsigned aH[2][4], aL[2][4];
            #pragma unroll
            for (int mt = 0; mt < 2; ++mt) {
                int rbase = mrowg + mt * 16;
                int p0 = s * 8 + lm;
                aH[mt][0] = AshH[(rbase + l4)     * ASTRIDE + p0];
                aH[mt][1] = AshH[(rbase + l4 + 8) * ASTRIDE + p0];
                aH[mt][2] = AshH[(rbase + l4)     * ASTRIDE + p0 + 4];
                aH[mt][3] = AshH[(rbase + l4 + 8) * ASTRIDE + p0 + 4];
                aL[mt][0] = AshL[(rbase + l4)     * ASTRIDE + p0];
                aL[mt][1] = AshL[(rbase + l4 + 8) * ASTRIDE + p0];
                aL[mt][2] = AshL[(rbase + l4)     * ASTRIDE + p0 + 4];
                aL[mt][3] = AshL[(rbase + l4 + 8) * ASTRIDE + p0 + 4];
            }
            #pragma unroll
            for (int nt = 0; nt < 8; ++nt) {
                int ntg = (ncolg >> 3) + nt;
                size_t idx = (((size_t)((L * 4 + kc) * 2 + s) * 16 + ntg) * 2) * 64 + lane * 2;
                uint2 bH = *reinterpret_cast<const uint2*>(&g_bfrag[idx]);
                uint2 bL = *reinterpret_cast<const uint2*>(&g_bfrag[idx + 64]);
                #pragma unroll
                for (int mt = 0; mt < 2; ++mt) {
                    mma_bf16(d[mt][nt], aH[mt], bH.x, bH.y);
                    mma_bf16(d[mt][nt], aH[mt], bL.x, bL.y);
                    mma_bf16(d[mt][nt], aL[mt], bH.x, bH.y);
                }
            }
        }
        __syncthreads();
    }

    #pragma unroll
    for (int mt = 0; mt < 2; ++mt) {
        int r_lo = row0 + mrowg + mt * 16 + l4;
        int r_hi = r_lo + 8;
        float s_lo = 1.f, s_hi = 1.f;
        if (dinv) {
            if (r_lo < nrows) s_lo = dinv[r_lo];
            if (r_hi < nrows) s_hi = dinv[r_hi];
        }
        #pragma unroll
        for (int nt = 0; nt < 8; ++nt) {
            int col = ncolg + nt * 8 + lm * 2;
            float b0 = 0.f, b1 = 0.f;
            if (bias) { b0 = bias[col]; b1 = bias[col + 1]; }
            float2 v0 = make_float2(d[mt][nt][0] * s_lo + b0, d[mt][nt][1] * s_lo + b1);
            float2 v1 = make_float2(d[mt][nt][2] * s_hi + b0, d[mt][nt][3] * s_hi + b1);
            if (do_relu) {
                v0.x = fmaxf(v0.x, 0.f); v0.y = fmaxf(v0.y, 0.f);
                v1.x = fmaxf(v1.x, 0.f); v1.y = fmaxf(v1.y, 0.f);
            }
            if (r_lo < nrows)
                *reinterpret_cast<float2*>(&out[r_lo * NF + col]) = v0;
            if (r_hi < nrows)
                *reinterpret_cast<float2*>(&out[r_hi * NF + col]) = v1;
        }
    }
}

// ---------------- aggregate: 2 warps/node (64-feature halves), 8-deep ILP ---
// MODE 0: y pre-scaled by dinv:  h = relu(dinv*(sum + self) + bias)
// MODE 1: as 0, then BN(eval) + per-graph atomicMax (no h store)
// MODE 2: y UNscaled: h = relu(dinv*(sum_src dinv[s]*y[s] + dinv*self) + bias)
template <int MODE>
__global__ __launch_bounds__(256)
void aggregate(const float* __restrict__ y, const float* __restrict__ bias,
               float* __restrict__ h,
               const int* __restrict__ batch,
               const float* __restrict__ gamma, const float* __restrict__ beta,
               const float* __restrict__ rmean, const float* __restrict__ rvar)
{
    int w    = threadIdx.x >> 5;            // 0..7
    int node = blockIdx.x * 4 + (w >> 1);
    int half = w & 1;
    int lane = threadIdx.x & 31;
    if (node >= N_NODES) return;

    int p0 = g_rowptr[node];
    int p1 = g_rowptr[node + 1];
    const int foff = half * 64 + lane * 2;   // this warp's 2-float slice

    float2 a = make_float2(0.f, 0.f);
    int e = p0;
    for (; e + 8 <= p1; e += 8) {
        int s[8];
        #pragma unroll
        for (int i = 0; i < 8; ++i) s[i] = g_csrc[e + i];
        float2 v[8];
        #pragma unroll
        for (int i = 0; i < 8; ++i)
            v[i] = *reinterpret_cast<const float2*>(&y[s[i] * NF + foff]);
        if (MODE == 2) {
            float dd[8];
            #pragma unroll
            for (int i = 0; i < 8; ++i) dd[i] = g_dinv[s[i]];
            #pragma unroll
            for (int i = 0; i < 8; ++i) { a.x += v[i].x * dd[i]; a.y += v[i].y * dd[i]; }
        } else {
            #pragma unroll
            for (int i = 0; i < 8; ++i) { a.x += v[i].x; a.y += v[i].y; }
        }
    }
    for (; e < p1; ++e) {
        int s = g_csrc[e];
        float2 v = *reinterpret_cast<const float2*>(&y[s * NF + foff]);
        float ds = (MODE == 2) ? g_dinv[s] : 1.f;
        a.x += v.x * ds; a.y += v.y * ds;
    }

    float2 self = *reinterpret_cast<const float2*>(&y[node * NF + foff]);
    float  di   = g_dinv[node];
    float  ss   = (MODE == 2) ? di : 1.f;
    float2 bv   = *reinterpret_cast<const float2*>(&bias[foff]);
    float2 o;
    o.x = fmaxf(di * (a.x + self.x * ss) + bv.x, 0.f);
    o.y = fmaxf(di * (a.y + self.y * ss) + bv.y, 0.f);

    if (MODE != 1) {
        *reinterpret_cast<float2*>(&h[node * NF + foff]) = o;
    } else {
        float2 gm = *reinterpret_cast<const float2*>(&gamma[foff]);
        float2 bt = *reinterpret_cast<const float2*>(&beta[foff]);
        float2 mu = *reinterpret_cast<const float2*>(&rmean[foff]);
        float2 va = *reinterpret_cast<const float2*>(&rvar[foff]);
        float vx = (o.x - mu.x) * rsqrtf(va.x + BN_EPS) * gm.x + bt.x;
        float vy = (o.y - mu.y) * rsqrtf(va.y + BN_EPS) * gm.y + bt.y;
        unsigned* p = &g_gmax[batch[node] * NF + foff];
        atomicMax(p + 0, enc_f(vx));
        atomicMax(p + 1, enc_f(vy));
    }
}

__global__ void decode_g() {
    int i = blockIdx.x * blockDim.x + threadIdx.x;
    if (i < NG * NF) g_g[i] = dec_f(g_gmax[i]);
}

// ---------------- small GEMM (one block per row) ---------------------------
__global__ void small_gemm(const float* __restrict__ A, const float* __restrict__ W,
                           const float* __restrict__ b, float* __restrict__ out,
                           int K, int ncols, int do_relu)
{
    __shared__ float xs[128];
    int row = blockIdx.x;
    for (int k = threadIdx.x; k < K; k += blockDim.x) xs[k] = A[row * K + k];
    __syncthreads();
    int c = threadIdx.x;
    if (c < ncols) {
        float s = b[c];
        for (int k = 0; k < K; ++k) s += xs[k] * W[k * ncols + c];
        out[row * ncols + c] = do_relu ? fmaxf(s, 0.f) : s;
    }
}

// ---------------- launch ---------------------------------------------------
extern "C" void kernel_launch(void* const* d_in, const int* in_sizes, int n_in,
                              void* d_out, int out_size)
{
    const float* x     = (const float*)d_in[0];
    const int*   ei    = (const int*)  d_in[1];
    const int*   batch = (const int*)  d_in[2];
    const float* W1 = (const float*)d_in[3];  const float* b1 = (const float*)d_in[4];
    const float* W2 = (const float*)d_in[5];  const float* b2 = (const float*)d_in[6];
    const float* W3 = (const float*)d_in[7];  const float* b3 = (const float*)d_in[8];
    const float* gamma = (const float*)d_in[9];
    const float* beta  = (const float*)d_in[10];
    const float* rmean = (const float*)d_in[11];
    const float* rvar  = (const float*)d_in[12];
    const float* lw1 = (const float*)d_in[13]; const float* lb1 = (const float*)d_in[14];
    const float* lw2 = (const float*)d_in[15]; const float* lb2 = (const float*)d_in[16];
    const float* lw3 = (const float*)d_in[17]; const float* lb3 = (const float*)d_in[18];
    float* out = (float*)d_out;

    const int* src = ei;
    const int* dst = ei + N_EDGES;

    void *p_dinv, *p_y, *p_h, *p_g, *p_m1, *p_m2;
    cudaGetSymbolAddress(&p_dinv, g_dinv);
    cudaGetSymbolAddress(&p_y,    g_y);
    cudaGetSymbolAddress(&p_h,    g_h);
    cudaGetSymbolAddress(&p_g,    g_g);
    cudaGetSymbolAddress(&p_m1,   g_m1);
    cudaGetSymbolAddress(&p_m2,   g_m2);
    float* y = (float*)p_y;
    float* h = (float*)p_h;
    const float* dinv = (const float*)p_dinv;

    const int EB = (N_EDGES + 255) / 256;
    const int ZB = (((N_NODES > NG * NF) ? N_NODES : NG * NF) + 255) / 256;
    const int GRID_GEMM = (N_NODES + 127) / 128;
    const int GRID_AGG  = (N_NODES + 3) / 4;

    // ---- fork: CSR build chain on a side stream, concurrent with gemm1 ----
    cudaStream_t s2;
    cudaEvent_t evA, evB;
    cudaStreamCreateWithFlags(&s2, cudaStreamNonBlocking);
    cudaEventCreateWithFlags(&evA, cudaEventDisableTiming);
    cudaEventCreateWithFlags(&evB, cudaEventDisableTiming);

    cudaEventRecord(evA, 0);
    cudaStreamWaitEvent(s2, evA, 0);
    zero_all<<<ZB, 256, 0, s2>>>();
    deg_count<<<EB, 256, 0, s2>>>(dst);
    scan_deg<<<1, 1024, 0, s2>>>();
    csr_fill<<<EB, 256, 0, s2>>>(src, dst);
    cudaEventRecord(evB, s2);

    // ---- main stream: weights + layer-1 GEMM (no dinv dependency) ----
    prep_w<<<(4 * NF * NF + 255) / 256, 256>>>(W1, W2, W3, lw1);
    gemm_mma<<<GRID_GEMM, 256>>>(x, 0, y, nullptr, nullptr, N_NODES, 0);

    // join CSR chain, then proceed
    cudaStreamWaitEvent(0, evB, 0);

    // layer 1 (aggregate applies dinv[src] itself)
    aggregate<2><<<GRID_AGG, 256>>>(y, b1, h, nullptr, nullptr, nullptr, nullptr, nullptr);
    // layer 2
    gemm_mma<<<GRID_GEMM, 256>>>(h, 1, y, dinv, nullptr, N_NODES, 0);
    aggregate<0><<<GRID_AGG, 256>>>(y, b2, h, nullptr, nullptr, nullptr, nullptr, nullptr);
    // layer 3 + BN + pool
    gemm_mma<<<GRID_GEMM, 256>>>(h, 2, y, dinv, nullptr, N_NODES, 0);
    aggregate<1><<<GRID_AGG, 256>>>(y, b3, nullptr, batch, gamma, beta, rmean, rvar);

    decode_g<<<(NG * NF + 255) / 256, 256>>>();

    // MLP head
    gemm_mma<<<(NG + 127) / 128, 256>>>((const float*)p_g, 3, (float*)p_m1,
                                        nullptr, lb1, NG, 1);
    small_gemm<<<NG, 64>>>((const float*)p_m1, lw2, lb2, (float*)p_m2, 128, 64, 1);
    small_gemm<<<NG, 64>>>((const float*)p_m2, lw3, lb3, out, 64, NC, 0);
}